// round 1
// baseline (speedup 1.0000x reference)
#include <cuda_runtime.h>

#define D_MODEL 1024
#define SEQ     2048
#define BATCH   4
#define BS_TOT  (BATCH * SEQ)   // 8192

// Scratch (device globals: allocation inside kernel_launch is forbidden)
__device__ float g_q[(size_t)BS_TOT * D_MODEL];
__device__ float g_k[(size_t)BS_TOT * D_MODEL];
__device__ float g_v[(size_t)BS_TOT * D_MODEL];
__device__ float g_s[(size_t)BATCH * SEQ * SEQ];
__device__ float g_attn[(size_t)BS_TOT * D_MODEL];

#define BM 128
#define BN 128
#define BK 8
#define TM 8
#define TN 8
// 256 threads per block; each thread computes an 8x8 micro-tile.

template<bool TRANS_B, bool HAS_BIAS>
__global__ __launch_bounds__(256)
void sgemm_kernel(const float* __restrict__ A, const float* __restrict__ B,
                  const float* __restrict__ bias, float* __restrict__ C,
                  int M, int N, int K, float alpha,
                  size_t sA, size_t sB, size_t sC)
{
    A += (size_t)blockIdx.z * sA;
    B += (size_t)blockIdx.z * sB;
    C += (size_t)blockIdx.z * sC;

    __shared__ float As[BK][BM];
    __shared__ float Bs[BK][BN];

    const int tid = threadIdx.x;
    const int bm  = blockIdx.y * BM;
    const int bn  = blockIdx.x * BN;
    const int tx  = tid % 16;       // 16 x 16 thread grid
    const int ty  = tid / 16;

    // A tile load mapping: 128 rows x 8 k-cols -> 2 float4 per row, 1 per thread
    const int a_row = tid >> 1;         // 0..127
    const int a_col = (tid & 1) * 4;    // 0 or 4
    // B tile load mapping (NN): 8 k-rows x 128 n-cols -> 1 float4 per thread
    const int b_row = tid >> 5;         // 0..7
    const int b_col = (tid & 31) * 4;   // 0..124

    float acc[TM][TN];
    #pragma unroll
    for (int i = 0; i < TM; i++)
        #pragma unroll
        for (int j = 0; j < TN; j++) acc[i][j] = 0.f;

    for (int k0 = 0; k0 < K; k0 += BK) {
        // Load A tile (transpose into As[k][m])
        float4 av = *(const float4*)(A + (size_t)(bm + a_row) * K + k0 + a_col);
        As[a_col + 0][a_row] = av.x;
        As[a_col + 1][a_row] = av.y;
        As[a_col + 2][a_row] = av.z;
        As[a_col + 3][a_row] = av.w;

        if (TRANS_B) {
            // B is [N, K] row-major; need Bs[k][n] = B[n][k]
            float4 bv = *(const float4*)(B + (size_t)(bn + a_row) * K + k0 + a_col);
            Bs[a_col + 0][a_row] = bv.x;
            Bs[a_col + 1][a_row] = bv.y;
            Bs[a_col + 2][a_row] = bv.z;
            Bs[a_col + 3][a_row] = bv.w;
        } else {
            // B is [K, N] row-major
            *(float4*)&Bs[b_row][b_col] =
                *(const float4*)(B + (size_t)(k0 + b_row) * N + bn + b_col);
        }
        __syncthreads();

        #pragma unroll
        for (int kk = 0; kk < BK; kk++) {
            float a[TM], b[TN];
            #pragma unroll
            for (int i = 0; i < TM; i += 4)
                *(float4*)&a[i] = *(float4*)&As[kk][ty * TM + i];
            #pragma unroll
            for (int j = 0; j < TN; j += 4)
                *(float4*)&b[j] = *(float4*)&Bs[kk][tx * TN + j];
            #pragma unroll
            for (int i = 0; i < TM; i++)
                #pragma unroll
                for (int j = 0; j < TN; j++)
                    acc[i][j] += a[i] * b[j];
        }
        __syncthreads();
    }

    #pragma unroll
    for (int i = 0; i < TM; i++) {
        size_t row = (size_t)(bm + ty * TM + i) * N;
        #pragma unroll
        for (int j = 0; j < TN; j += 4) {
            int col = bn + tx * TN + j;
            float4 v;
            v.x = acc[i][j + 0] * alpha;
            v.y = acc[i][j + 1] * alpha;
            v.z = acc[i][j + 2] * alpha;
            v.w = acc[i][j + 3] * alpha;
            if (HAS_BIAS) {
                v.x += bias[col + 0];
                v.y += bias[col + 1];
                v.z += bias[col + 2];
                v.w += bias[col + 3];
            }
            *(float4*)(C + row + col) = v;
        }
    }
}

// Row softmax over g_s: one block per row (SEQ = 2048 cols, 256 threads x 8).
// Row held in registers: one global read + one global write.
__global__ __launch_bounds__(256)
void softmax_kernel(float* __restrict__ S)
{
    float* row = S + (size_t)blockIdx.x * SEQ;
    const int tid = threadIdx.x;

    float v[8];
    float m = -3.4e38f;
    #pragma unroll
    for (int i = 0; i < 8; i++) {
        v[i] = row[tid + i * 256];
        m = fmaxf(m, v[i]);
    }

    __shared__ float red[8];
    #pragma unroll
    for (int o = 16; o > 0; o >>= 1)
        m = fmaxf(m, __shfl_xor_sync(0xffffffffu, m, o));
    if ((tid & 31) == 0) red[tid >> 5] = m;
    __syncthreads();
    m = red[0];
    #pragma unroll
    for (int w = 1; w < 8; w++) m = fmaxf(m, red[w]);
    __syncthreads();   // red reused below

    float s = 0.f;
    #pragma unroll
    for (int i = 0; i < 8; i++) {
        v[i] = __expf(v[i] - m);
        s += v[i];
    }
    #pragma unroll
    for (int o = 16; o > 0; o >>= 1)
        s += __shfl_xor_sync(0xffffffffu, s, o);
    if ((tid & 31) == 0) red[tid >> 5] = s;
    __syncthreads();
    s = 0.f;
    #pragma unroll
    for (int w = 0; w < 8; w++) s += red[w];

    const float inv = 1.f / s;
    #pragma unroll
    for (int i = 0; i < 8; i++)
        row[tid + i * 256] = v[i] * inv;
}

extern "C" void kernel_launch(void* const* d_in, const int* in_sizes, int n_in,
                              void* d_out, int out_size)
{
    const float* x  = (const float*)d_in[0];
    const float* Wq = (const float*)d_in[1];
    const float* bq = (const float*)d_in[2];
    const float* Wk = (const float*)d_in[3];
    const float* bk = (const float*)d_in[4];
    const float* Wv = (const float*)d_in[5];
    const float* bv = (const float*)d_in[6];
    const float* Wo = (const float*)d_in[7];
    const float* bo = (const float*)d_in[8];
    float* out = (float*)d_out;

    float *q, *k, *v, *s, *attn;
    cudaGetSymbolAddress((void**)&q,    g_q);
    cudaGetSymbolAddress((void**)&k,    g_k);
    cudaGetSymbolAddress((void**)&v,    g_v);
    cudaGetSymbolAddress((void**)&s,    g_s);
    cudaGetSymbolAddress((void**)&attn, g_attn);

    const dim3 blk(256);

    // ---- QKV projections: [8192,1024] x [1024,1024] + bias ----
    const dim3 gproj(D_MODEL / BN, BS_TOT / BM, 1);
    sgemm_kernel<false, true><<<gproj, blk>>>(x, Wq, bq, q,
        BS_TOT, D_MODEL, D_MODEL, 1.f, 0, 0, 0);
    sgemm_kernel<false, true><<<gproj, blk>>>(x, Wk, bk, k,
        BS_TOT, D_MODEL, D_MODEL, 1.f, 0, 0, 0);
    sgemm_kernel<false, true><<<gproj, blk>>>(x, Wv, bv, v,
        BS_TOT, D_MODEL, D_MODEL, 1.f, 0, 0, 0);

    // ---- scores = q @ k^T / sqrt(d): batched NT GEMM ----
    const dim3 gsc(SEQ / BN, SEQ / BM, BATCH);
    sgemm_kernel<true, false><<<gsc, blk>>>(q, k, nullptr, s,
        SEQ, SEQ, D_MODEL, 0.03125f,
        (size_t)SEQ * D_MODEL, (size_t)SEQ * D_MODEL, (size_t)SEQ * SEQ);

    // ---- softmax over rows ----
    softmax_kernel<<<BATCH * SEQ, blk>>>(s);

    // ---- attn = p @ v: batched NN GEMM ----
    const dim3 gpv(D_MODEL / BN, SEQ / BM, BATCH);
    sgemm_kernel<false, false><<<gpv, blk>>>(s, v, nullptr, attn,
        SEQ, D_MODEL, SEQ, 1.f,
        (size_t)SEQ * SEQ, (size_t)SEQ * D_MODEL, (size_t)SEQ * D_MODEL);

    // ---- out = attn @ Wo + bo ----
    sgemm_kernel<false, true><<<gproj, blk>>>(attn, Wo, bo, out,
        BS_TOT, D_MODEL, D_MODEL, 1.f, 0, 0, 0);
}

// round 3
// speedup vs baseline: 2.3248x; 2.3248x over previous
#include <cuda_runtime.h>
#include <cuda_bf16.h>
#include <cstdint>

#define D_MODEL 1024
#define SEQ     2048
#define BATCH   4
#define BS_TOT  8192

// ---------------- scratch (device globals; no allocations allowed) ----------
__device__ __align__(16) __nv_bfloat16 g_xs[(size_t)BS_TOT * 2 * D_MODEL];        // x split  [8192][2048]
__device__ __align__(16) __nv_bfloat16 g_wt[4][(size_t)D_MODEL * 2 * D_MODEL];    // W^T split [1024][2048] x4
__device__ __align__(16) __nv_bfloat16 g_qs[(size_t)BS_TOT * 2 * D_MODEL];        // q split (pre-scaled 1/32)
__device__ __align__(16) __nv_bfloat16 g_ks[(size_t)BS_TOT * 2 * D_MODEL];        // k split
__device__ __align__(16) float         g_vf[(size_t)BS_TOT * D_MODEL];            // v fp32
__device__ __align__(16) __nv_bfloat16 g_vts[(size_t)BATCH * D_MODEL * 2 * SEQ];  // v^T split [b][1024][4096]
__device__ __align__(16) float         g_sc[(size_t)BATCH * SEQ * SEQ];           // scores fp32
__device__ __align__(16) __nv_bfloat16 g_ps[(size_t)BATCH * SEQ * 2 * SEQ];       // softmax split
__device__ __align__(16) __nv_bfloat16 g_as[(size_t)BS_TOT * 2 * D_MODEL];        // attn split

// ---------------- helpers ----------------
__device__ __forceinline__ uint32_t s2u(const void* p) {
    uint32_t a;
    asm("{ .reg .u64 t; cvta.to.shared.u64 t, %1; cvt.u32.u64 %0, t; }" : "=r"(a) : "l"(p));
    return a;
}

// smem tile: 128 rows x 32 bf16 (64B rows = 4 x 16B chunks), XOR swizzle.
__device__ __forceinline__ uint32_t swz(int row, int chunk) {
    return (uint32_t)(row * 64 + ((chunk ^ ((row >> 1) & 3)) << 4));
}

__device__ __forceinline__ void ldsm4(uint32_t (&r)[4], uint32_t a) {
    asm volatile("ldmatrix.sync.aligned.m8n8.x4.shared.b16 {%0,%1,%2,%3}, [%4];"
                 : "=r"(r[0]), "=r"(r[1]), "=r"(r[2]), "=r"(r[3]) : "r"(a));
}

__device__ __forceinline__ void mma16816(float (&d)[4], const uint32_t (&a)[4],
                                         uint32_t b0, uint32_t b1) {
    asm volatile(
        "mma.sync.aligned.m16n8k16.row.col.f32.bf16.bf16.f32 "
        "{%0,%1,%2,%3}, {%4,%5,%6,%7}, {%8,%9}, {%0,%1,%2,%3};"
        : "+f"(d[0]), "+f"(d[1]), "+f"(d[2]), "+f"(d[3])
        : "r"(a[0]), "r"(a[1]), "r"(a[2]), "r"(a[3]), "r"(b0), "r"(b1));
}

// ---------------- bf16 hi/lo split GEMM: D = A * B^T -----------------------
// A: [M][2K] bf16 ([hi|lo] along K), B: [N][2K] bf16, both K-contiguous.
// 3-term product: hi*hi + lo*hi + hi*lo (lo*lo dropped, ~2^-16 rel).
#define BM 128
#define BN 128
#define BK 32
#define TILE_B  8192                 // 128 rows * 64B
#define STAGE_B (4 * TILE_B)         // Ahi, Alo, Bhi, Blo = 32KB
#define STAGES  3
#define GEMM_SMEM (STAGES * STAGE_B) // 96KB

// load one 128x32 half-tile (hi or lo) via cp.async; ld in elements.
__device__ __forceinline__ void ld_half(uint32_t sdst, const __nv_bfloat16* src,
                                        size_t ld, int tid) {
#pragma unroll
    for (int j = 0; j < 2; j++) {
        int u = tid + 256 * j;
        int r = u >> 2, c = u & 3;
        uint32_t dst = sdst + swz(r, c);
        const void* s = src + (size_t)r * ld + c * 8;
        asm volatile("cp.async.cg.shared.global [%0], [%1], 16;" :: "r"(dst), "l"(s));
    }
}

template<bool SPLIT_OUT, bool HAS_BIAS>
__global__ __launch_bounds__(256)
void gemm_mma(const __nv_bfloat16* __restrict__ A,
              const __nv_bfloat16* __restrict__ B,
              const float* __restrict__ bias,
              void* __restrict__ Cg,
              int N, int K, float alpha,
              size_t sA, size_t sB, size_t sC)
{
    extern __shared__ __align__(128) char smem[];
    const uint32_t sb = s2u(smem);
    const int tid = threadIdx.x, lane = tid & 31, wid = tid >> 5;
    const int wm = wid & 1, wn = wid >> 1;         // 2 x 4 warp grid
    const size_t lda = 2 * (size_t)K;

    A += blockIdx.z * sA + (size_t)blockIdx.y * BM * lda;
    B += blockIdx.z * sB + (size_t)blockIdx.x * BN * lda;

    float acc[4][4][4];
#pragma unroll
    for (int i = 0; i < 4; i++)
#pragma unroll
        for (int j = 0; j < 4; j++)
#pragma unroll
            for (int t = 0; t < 4; t++) acc[i][j][t] = 0.f;

    const int NC = K >> 5;

    // prologue: chunks 0,1
#pragma unroll
    for (int c = 0; c < 2; c++) {
        uint32_t st = sb + c * STAGE_B;
        ld_half(st,              A + c * 32,     lda, tid);
        ld_half(st + TILE_B,     A + K + c * 32, lda, tid);
        ld_half(st + 2 * TILE_B, B + c * 32,     lda, tid);
        ld_half(st + 3 * TILE_B, B + K + c * 32, lda, tid);
        asm volatile("cp.async.commit_group;" ::: "memory");
    }

    for (int i = 0; i < NC; i++) {
        asm volatile("cp.async.wait_group 1;" ::: "memory");
        __syncthreads();

        if (i + 2 < NC) {
            int c = i + 2;
            uint32_t st = sb + (c % 3) * STAGE_B;
            ld_half(st,              A + c * 32,     lda, tid);
            ld_half(st + TILE_B,     A + K + c * 32, lda, tid);
            ld_half(st + 2 * TILE_B, B + c * 32,     lda, tid);
            ld_half(st + 3 * TILE_B, B + K + c * 32, lda, tid);
        }
        asm volatile("cp.async.commit_group;" ::: "memory");

        uint32_t st   = sb + (i % 3) * STAGE_B;
        uint32_t sAhi = st, sAlo = st + TILE_B;
        uint32_t sBhi = st + 2 * TILE_B, sBlo = st + 3 * TILE_B;

#pragma unroll
        for (int ks = 0; ks < 2; ks++) {           // two k16 steps per chunk
            const int arow = lane & 15;
            const int achk = ks * 2 + (lane >> 4);

            uint32_t ahi[4][4], alo[4][4], bhi[2][4], blo[2][4];
#pragma unroll
            for (int mt = 0; mt < 4; mt++)
                ldsm4(ahi[mt], sAhi + swz(wm * 64 + mt * 16 + arow, achk));
#pragma unroll
            for (int nt2 = 0; nt2 < 2; nt2++)
                ldsm4(bhi[nt2], sBhi + swz(wn * 32 + nt2 * 16 + arow, achk));
#pragma unroll
            for (int mt = 0; mt < 4; mt++)
                ldsm4(alo[mt], sAlo + swz(wm * 64 + mt * 16 + arow, achk));
#pragma unroll
            for (int nt2 = 0; nt2 < 2; nt2++)
                ldsm4(blo[nt2], sBlo + swz(wn * 32 + nt2 * 16 + arow, achk));

#pragma unroll
            for (int mt = 0; mt < 4; mt++)
#pragma unroll
                for (int nt = 0; nt < 4; nt++) {
                    const int n2 = nt >> 1, sub = nt & 1;
                    mma16816(acc[mt][nt], ahi[mt], bhi[n2][sub], bhi[n2][sub + 2]);
                    mma16816(acc[mt][nt], alo[mt], bhi[n2][sub], bhi[n2][sub + 2]);
                    mma16816(acc[mt][nt], ahi[mt], blo[n2][sub], blo[n2][sub + 2]);
                }
        }
    }

    // ---- epilogue ----
    const int gm0 = blockIdx.y * BM + wm * 64;
    const int gn0 = blockIdx.x * BN + wn * 32;
    const int rq = lane >> 2, cq = (lane & 3) * 2;

#pragma unroll
    for (int mt = 0; mt < 4; mt++)
#pragma unroll
        for (int nt = 0; nt < 4; nt++)
#pragma unroll
            for (int h = 0; h < 2; h++) {
                const int row = gm0 + mt * 16 + rq + h * 8;
                const int col = gn0 + nt * 8 + cq;
                float v0 = acc[mt][nt][h * 2 + 0];
                float v1 = acc[mt][nt][h * 2 + 1];
                if (HAS_BIAS) { v0 += __ldg(&bias[col]); v1 += __ldg(&bias[col + 1]); }
                v0 *= alpha; v1 *= alpha;
                if (SPLIT_OUT) {
                    __nv_bfloat16* C = (__nv_bfloat16*)Cg + blockIdx.z * sC
                                     + (size_t)row * (2 * (size_t)N) + col;
                    __nv_bfloat16 h0 = __float2bfloat16(v0), h1 = __float2bfloat16(v1);
                    __nv_bfloat16 l0 = __float2bfloat16(v0 - __bfloat162float(h0));
                    __nv_bfloat16 l1 = __float2bfloat16(v1 - __bfloat162float(h1));
                    *(__nv_bfloat162*)(C)     = __halves2bfloat162(h0, h1);
                    *(__nv_bfloat162*)(C + N) = __halves2bfloat162(l0, l1);
                } else {
                    float* C = (float*)Cg + blockIdx.z * sC + (size_t)row * (size_t)N + col;
                    float2 v; v.x = v0; v.y = v1;
                    *(float2*)C = v;
                }
            }
}

// ---------------- conversion kernels ----------------------------------------
__global__ __launch_bounds__(256)
void split_rows_k(const float* __restrict__ in, __nv_bfloat16* __restrict__ out, int K)
{
    size_t i = (size_t)blockIdx.x * blockDim.x + threadIdx.x;
    int kq = K >> 2;
    size_t m = i / kq;
    int k4 = (int)(i % kq) << 2;
    float4 v = *(const float4*)(in + m * K + k4);
    __nv_bfloat16 h0 = __float2bfloat16(v.x), h1 = __float2bfloat16(v.y);
    __nv_bfloat16 h2 = __float2bfloat16(v.z), h3 = __float2bfloat16(v.w);
    __nv_bfloat16 l0 = __float2bfloat16(v.x - __bfloat162float(h0));
    __nv_bfloat16 l1 = __float2bfloat16(v.y - __bfloat162float(h1));
    __nv_bfloat16 l2 = __float2bfloat16(v.z - __bfloat162float(h2));
    __nv_bfloat16 l3 = __float2bfloat16(v.w - __bfloat162float(h3));
    __nv_bfloat16* o = out + m * 2 * (size_t)K + k4;
    *(__nv_bfloat162*)(o)         = __halves2bfloat162(h0, h1);
    *(__nv_bfloat162*)(o + 2)     = __halves2bfloat162(h2, h3);
    *(__nv_bfloat162*)(o + K)     = __halves2bfloat162(l0, l1);
    *(__nv_bfloat162*)(o + K + 2) = __halves2bfloat162(l2, l3);
}

__global__ void transpose_split_k(const float* __restrict__ in,
                                  __nv_bfloat16* __restrict__ out,
                                  int R, int C, size_t sIn, size_t sOut)
{
    in  += blockIdx.z * sIn;
    out += blockIdx.z * sOut;
    __shared__ float t[32][33];
    int r0 = blockIdx.y * 32, c0 = blockIdx.x * 32;
    t[threadIdx.y][threadIdx.x] = in[(size_t)(r0 + threadIdx.y) * C + c0 + threadIdx.x];
    __syncthreads();
    float v = t[threadIdx.x][threadIdx.y];
    __nv_bfloat16 h = __float2bfloat16(v);
    __nv_bfloat16 l = __float2bfloat16(v - __bfloat162float(h));
    size_t o = (size_t)(c0 + threadIdx.y) * (2 * (size_t)R) + r0 + threadIdx.x;
    out[o]     = h;
    out[o + R] = l;
}

__global__ __launch_bounds__(256)
void softmax_split_k(const float* __restrict__ S, __nv_bfloat16* __restrict__ P)
{
    const float* row = S + (size_t)blockIdx.x * SEQ;
    __nv_bfloat16* prow = P + (size_t)blockIdx.x * (2 * SEQ);
    const int tid = threadIdx.x;

    float v[8];
    float m = -3.4e38f;
#pragma unroll
    for (int i = 0; i < 8; i++) { v[i] = row[tid + i * 256]; m = fmaxf(m, v[i]); }

    __shared__ float red[8];
#pragma unroll
    for (int o = 16; o > 0; o >>= 1) m = fmaxf(m, __shfl_xor_sync(0xffffffffu, m, o));
    if ((tid & 31) == 0) red[tid >> 5] = m;
    __syncthreads();
    m = red[0];
#pragma unroll
    for (int w = 1; w < 8; w++) m = fmaxf(m, red[w]);
    __syncthreads();

    float s = 0.f;
#pragma unroll
    for (int i = 0; i < 8; i++) { v[i] = __expf(v[i] - m); s += v[i]; }
#pragma unroll
    for (int o = 16; o > 0; o >>= 1) s += __shfl_xor_sync(0xffffffffu, s, o);
    if ((tid & 31) == 0) red[tid >> 5] = s;
    __syncthreads();
    s = 0.f;
#pragma unroll
    for (int w = 0; w < 8; w++) s += red[w];
    const float inv = 1.f / s;

#pragma unroll
    for (int i = 0; i < 8; i++) {
        float p = v[i] * inv;
        __nv_bfloat16 h = __float2bfloat16(p);
        __nv_bfloat16 l = __float2bfloat16(p - __bfloat162float(h));
        prow[tid + i * 256]       = h;
        prow[SEQ + tid + i * 256] = l;
    }
}

// ---------------- host launcher ----------------------------------------------
extern "C" void kernel_launch(void* const* d_in, const int* in_sizes, int n_in,
                              void* d_out, int out_size)
{
    const float* x  = (const float*)d_in[0];
    const float* Wq = (const float*)d_in[1];
    const float* bq = (const float*)d_in[2];
    const float* Wk = (const float*)d_in[3];
    const float* bk = (const float*)d_in[4];
    const float* Wv = (const float*)d_in[5];
    const float* bv = (const float*)d_in[6];
    const float* Wo = (const float*)d_in[7];
    const float* bo = (const float*)d_in[8];
    float* out = (float*)d_out;

    __nv_bfloat16 *xs, *wt, *qs, *ks, *vts, *ps, *as;
    float *vf, *sc;
    cudaGetSymbolAddress((void**)&xs,  g_xs);
    cudaGetSymbolAddress((void**)&wt,  g_wt);
    cudaGetSymbolAddress((void**)&qs,  g_qs);
    cudaGetSymbolAddress((void**)&ks,  g_ks);
    cudaGetSymbolAddress((void**)&vf,  g_vf);
    cudaGetSymbolAddress((void**)&vts, g_vts);
    cudaGetSymbolAddress((void**)&sc,  g_sc);
    cudaGetSymbolAddress((void**)&ps,  g_ps);
    cudaGetSymbolAddress((void**)&as,  g_as);
    const size_t WSTRIDE = (size_t)D_MODEL * 2 * D_MODEL;

    cudaFuncSetAttribute(gemm_mma<true,  true>,  cudaFuncAttributeMaxDynamicSharedMemorySize, GEMM_SMEM);
    cudaFuncSetAttribute(gemm_mma<false, true>,  cudaFuncAttributeMaxDynamicSharedMemorySize, GEMM_SMEM);
    cudaFuncSetAttribute(gemm_mma<false, false>, cudaFuncAttributeMaxDynamicSharedMemorySize, GEMM_SMEM);
    cudaFuncSetAttribute(gemm_mma<true,  false>, cudaFuncAttributeMaxDynamicSharedMemorySize, GEMM_SMEM);

    // 1. split x
    split_rows_k<<<(BS_TOT * (D_MODEL / 4)) / 256, 256>>>(x, xs, D_MODEL);

    // 2. transpose+split weights -> W^T as [out][2*in]
    dim3 tb(32, 32);
    transpose_split_k<<<dim3(32, 32, 1), tb>>>(Wq, wt + 0 * WSTRIDE, D_MODEL, D_MODEL, 0, 0);
    transpose_split_k<<<dim3(32, 32, 1), tb>>>(Wk, wt + 1 * WSTRIDE, D_MODEL, D_MODEL, 0, 0);
    transpose_split_k<<<dim3(32, 32, 1), tb>>>(Wv, wt + 2 * WSTRIDE, D_MODEL, D_MODEL, 0, 0);
    transpose_split_k<<<dim3(32, 32, 1), tb>>>(Wo, wt + 3 * WSTRIDE, D_MODEL, D_MODEL, 0, 0);

    // 3. projections: M=8192, N=1024, K=1024
    const dim3 gproj(D_MODEL / BN, BS_TOT / BM, 1);
    gemm_mma<true, true><<<gproj, 256, GEMM_SMEM>>>(xs, wt + 0 * WSTRIDE, bq, qs,
        D_MODEL, D_MODEL, 0.03125f, 0, 0, 0);
    gemm_mma<true, true><<<gproj, 256, GEMM_SMEM>>>(xs, wt + 1 * WSTRIDE, bk, ks,
        D_MODEL, D_MODEL, 1.0f, 0, 0, 0);
    gemm_mma<false, true><<<gproj, 256, GEMM_SMEM>>>(xs, wt + 2 * WSTRIDE, bv, vf,
        D_MODEL, D_MODEL, 1.0f, 0, 0, 0);

    // 4. scores = q_scaled @ k^T (batched): M=N=2048, K=1024
    const dim3 gsc(SEQ / BN, SEQ / BM, BATCH);
    gemm_mma<false, false><<<gsc, 256, GEMM_SMEM>>>(qs, ks, nullptr, sc,
        SEQ, D_MODEL, 1.0f,
        (size_t)SEQ * 2 * D_MODEL, (size_t)SEQ * 2 * D_MODEL, (size_t)SEQ * SEQ);

    // 5. softmax (+split)
    softmax_split_k<<<BATCH * SEQ, 256>>>(sc, ps);

    // 6. v^T split per batch
    transpose_split_k<<<dim3(D_MODEL / 32, SEQ / 32, BATCH), tb>>>(vf, vts,
        SEQ, D_MODEL, (size_t)SEQ * D_MODEL, (size_t)D_MODEL * 2 * SEQ);

    // 7. attn = p @ v (batched): M=2048, N=1024, K=2048
    const dim3 gpv(D_MODEL / BN, SEQ / BM, BATCH);
    gemm_mma<true, false><<<gpv, 256, GEMM_SMEM>>>(ps, vts, nullptr, as,
        D_MODEL, SEQ, 1.0f,
        (size_t)SEQ * 2 * SEQ, (size_t)D_MODEL * 2 * SEQ, (size_t)SEQ * 2 * D_MODEL);

    // 8. out = attn @ Wo + bo
    gemm_mma<false, true><<<gproj, 256, GEMM_SMEM>>>(as, wt + 3 * WSTRIDE, bo, out,
        D_MODEL, D_MODEL, 1.0f, 0, 0, 0);
}

// round 4
// speedup vs baseline: 3.7403x; 1.6089x over previous
#include <cuda_runtime.h>
#include <cuda_fp16.h>
#include <cstdint>

#define D_MODEL 1024
#define SEQ     2048
#define BATCH   4
#define BS_TOT  8192

// ---------------- scratch (device globals; no allocations allowed) ----------
__device__ __align__(16) __half g_xs[(size_t)BS_TOT * 2 * D_MODEL];        // x split  [8192][2048]
__device__ __align__(16) __half g_wt[4][(size_t)D_MODEL * 2 * D_MODEL];    // W^T split [1024][2048] x4
__device__ __align__(16) __half g_qs[(size_t)BS_TOT * 2 * D_MODEL];        // q split (pre-scaled 1/32)
__device__ __align__(16) __half g_ks[(size_t)BS_TOT * D_MODEL];            // k hi-only [8192][1024]
__device__ __align__(16) __half g_vts[(size_t)BATCH * D_MODEL * SEQ];      // v^T hi-only [b][1024][2048]
__device__ __align__(16) float  g_sc[(size_t)BATCH * SEQ * SEQ];           // scores fp32
__device__ __align__(16) __half g_ps[(size_t)BATCH * SEQ * 2 * SEQ];       // softmax split
__device__ __align__(16) __half g_as[(size_t)BS_TOT * 2 * D_MODEL];        // attn split

// ---------------- helpers ----------------
__device__ __forceinline__ uint32_t s2u(const void* p) {
    uint32_t a;
    asm("{ .reg .u64 t; cvta.to.shared.u64 t, %1; cvt.u32.u64 %0, t; }" : "=r"(a) : "l"(p));
    return a;
}

// smem tile: 128 rows x 32 fp16 (64B rows = 4 x 16B chunks), XOR swizzle.
__device__ __forceinline__ uint32_t swz(int row, int chunk) {
    return (uint32_t)(row * 64 + ((chunk ^ ((row >> 1) & 3)) << 4));
}

__device__ __forceinline__ void ldsm4(uint32_t (&r)[4], uint32_t a) {
    asm volatile("ldmatrix.sync.aligned.m8n8.x4.shared.b16 {%0,%1,%2,%3}, [%4];"
                 : "=r"(r[0]), "=r"(r[1]), "=r"(r[2]), "=r"(r[3]) : "r"(a));
}

__device__ __forceinline__ void mma16816(float (&d)[4], const uint32_t (&a)[4],
                                         uint32_t b0, uint32_t b1) {
    asm volatile(
        "mma.sync.aligned.m16n8k16.row.col.f32.f16.f16.f32 "
        "{%0,%1,%2,%3}, {%4,%5,%6,%7}, {%8,%9}, {%0,%1,%2,%3};"
        : "+f"(d[0]), "+f"(d[1]), "+f"(d[2]), "+f"(d[3])
        : "r"(a[0]), "r"(a[1]), "r"(a[2]), "r"(a[3]), "r"(b0), "r"(b1));
}

__device__ __forceinline__ void split_h(float v, __half& h, __half& l) {
    h = __float2half_rn(v);
    l = __float2half_rn(v - __half2float(h));
}

// ---------------- fp16 hi/lo split GEMM: D = A * B^T ------------------------
// A: [M][2K] fp16 ([hi|lo] along K, lda = 2K). B: [N rows][ldb] fp16, hi in
// cols [0,K). 2-term product: a_hi*b_hi + a_lo*b_hi  (b_lo never stored).
#define BM 128
#define BN 128
#define TILE_B  8192                 // 128 rows * 64B
#define STAGE_B (3 * TILE_B)         // Ahi, Alo, Bhi = 24KB
#define GEMM_SMEM (3 * STAGE_B)      // 3 stages = 72KB

// OUT modes
#define OUT_F32   0
#define OUT_SPLIT 1   // half [m][2N], hi|lo
#define OUT_HALF  2   // half [m][N]
#define OUT_VT    3   // half, col n -> (b = n>>11, t = n&2047): C[b][row][t]; bias by row

__device__ __forceinline__ void ld_half(uint32_t sdst, const __half* src,
                                        size_t ld, int tid) {
#pragma unroll
    for (int j = 0; j < 2; j++) {
        int u = tid + 256 * j;
        int r = u >> 2, c = u & 3;
        uint32_t dst = sdst + swz(r, c);
        const void* s = src + (size_t)r * ld + c * 8;
        asm volatile("cp.async.cg.shared.global [%0], [%1], 16;" :: "r"(dst), "l"(s));
    }
}

template<int MODE, bool HAS_BIAS>
__global__ __launch_bounds__(256, 2)
void gemm_mma(const __half* __restrict__ A,
              const __half* __restrict__ B,
              const float* __restrict__ bias,
              void* __restrict__ Cg,
              int N, int K, int ldb, float alpha,
              size_t sA, size_t sB, size_t sC)
{
    extern __shared__ __align__(128) char smem[];
    const uint32_t sb = s2u(smem);
    const int tid = threadIdx.x, lane = tid & 31, wid = tid >> 5;
    const int wm = wid & 1, wn = wid >> 1;          // 2 x 4 warp grid
    const size_t lda = 2 * (size_t)K;

    A += blockIdx.z * sA + (size_t)blockIdx.y * BM * lda;
    B += blockIdx.z * sB + (size_t)blockIdx.x * BN * (size_t)ldb;

    float acc[4][4][4];
#pragma unroll
    for (int i = 0; i < 4; i++)
#pragma unroll
        for (int j = 0; j < 4; j++)
#pragma unroll
            for (int t = 0; t < 4; t++) acc[i][j][t] = 0.f;

    const int NC = K >> 5;

#pragma unroll
    for (int c = 0; c < 2; c++) {
        uint32_t st = sb + c * STAGE_B;
        ld_half(st,              A + c * 32,     lda, tid);
        ld_half(st + TILE_B,     A + K + c * 32, lda, tid);
        ld_half(st + 2 * TILE_B, B + c * 32,     ldb, tid);
        asm volatile("cp.async.commit_group;" ::: "memory");
    }

    for (int i = 0; i < NC; i++) {
        asm volatile("cp.async.wait_group 1;" ::: "memory");
        __syncthreads();

        if (i + 2 < NC) {
            int c = i + 2;
            uint32_t st = sb + (c % 3) * STAGE_B;
            ld_half(st,              A + c * 32,     lda, tid);
            ld_half(st + TILE_B,     A + K + c * 32, lda, tid);
            ld_half(st + 2 * TILE_B, B + c * 32,     ldb, tid);
        }
        asm volatile("cp.async.commit_group;" ::: "memory");

        uint32_t st   = sb + (i % 3) * STAGE_B;
        uint32_t sAhi = st, sAlo = st + TILE_B, sBhi = st + 2 * TILE_B;

#pragma unroll
        for (int ks = 0; ks < 2; ks++) {            // two k16 steps per chunk
            const int arow = lane & 15;
            const int achk = ks * 2 + (lane >> 4);

            uint32_t ahi[4][4], alo[4][4], bh[2][4];
#pragma unroll
            for (int mt = 0; mt < 4; mt++)
                ldsm4(ahi[mt], sAhi + swz(wm * 64 + mt * 16 + arow, achk));
#pragma unroll
            for (int nt2 = 0; nt2 < 2; nt2++)
                ldsm4(bh[nt2], sBhi + swz(wn * 32 + nt2 * 16 + arow, achk));
#pragma unroll
            for (int mt = 0; mt < 4; mt++)
                ldsm4(alo[mt], sAlo + swz(wm * 64 + mt * 16 + arow, achk));

            // term-outer: 16 independent accumulators between reuses
#pragma unroll
            for (int mt = 0; mt < 4; mt++)
#pragma unroll
                for (int nt = 0; nt < 4; nt++) {
                    const int n2 = nt >> 1, sub = nt & 1;
                    mma16816(acc[mt][nt], ahi[mt], bh[n2][sub], bh[n2][sub + 2]);
                }
#pragma unroll
            for (int mt = 0; mt < 4; mt++)
#pragma unroll
                for (int nt = 0; nt < 4; nt++) {
                    const int n2 = nt >> 1, sub = nt & 1;
                    mma16816(acc[mt][nt], alo[mt], bh[n2][sub], bh[n2][sub + 2]);
                }
        }
    }

    // ---- epilogue ----
    const int gm0 = blockIdx.y * BM + wm * 64;
    const int gn0 = blockIdx.x * BN + wn * 32;
    const int rq = lane >> 2, cq = (lane & 3) * 2;

#pragma unroll
    for (int mt = 0; mt < 4; mt++)
#pragma unroll
        for (int nt = 0; nt < 4; nt++)
#pragma unroll
            for (int h = 0; h < 2; h++) {
                const int row = gm0 + mt * 16 + rq + h * 8;
                const int col = gn0 + nt * 8 + cq;
                float v0 = acc[mt][nt][h * 2 + 0];
                float v1 = acc[mt][nt][h * 2 + 1];
                if (HAS_BIAS) {
                    if (MODE == OUT_VT) { float b = __ldg(&bias[row]); v0 += b; v1 += b; }
                    else { v0 += __ldg(&bias[col]); v1 += __ldg(&bias[col + 1]); }
                }
                v0 *= alpha; v1 *= alpha;
                if (MODE == OUT_SPLIT) {
                    __half* C = (__half*)Cg + blockIdx.z * sC
                              + (size_t)row * (2 * (size_t)N) + col;
                    __half h0, l0, h1, l1;
                    split_h(v0, h0, l0); split_h(v1, h1, l1);
                    *(__half2*)(C)     = __halves2half2(h0, h1);
                    *(__half2*)(C + N) = __halves2half2(l0, l1);
                } else if (MODE == OUT_HALF) {
                    __half* C = (__half*)Cg + blockIdx.z * sC + (size_t)row * (size_t)N + col;
                    *(__half2*)C = __halves2half2(__float2half_rn(v0), __float2half_rn(v1));
                } else if (MODE == OUT_VT) {
                    const int b = col >> 11, t = col & 2047;
                    __half* C = (__half*)Cg + (size_t)b * D_MODEL * SEQ
                              + (size_t)row * SEQ + t;
                    *(__half2*)C = __halves2half2(__float2half_rn(v0), __float2half_rn(v1));
                } else {
                    float* C = (float*)Cg + blockIdx.z * sC + (size_t)row * (size_t)N + col;
                    float2 v; v.x = v0; v.y = v1;
                    *(float2*)C = v;
                }
            }
}

// ---------------- conversion kernels ----------------------------------------
__global__ __launch_bounds__(256)
void split_rows_h(const float* __restrict__ in, __half* __restrict__ out, int K)
{
    size_t i = (size_t)blockIdx.x * blockDim.x + threadIdx.x;
    int kq = K >> 2;
    size_t m = i / kq;
    int k4 = (int)(i % kq) << 2;
    float4 v = *(const float4*)(in + m * K + k4);
    __half h0, l0, h1, l1, h2, l2, h3, l3;
    split_h(v.x, h0, l0); split_h(v.y, h1, l1);
    split_h(v.z, h2, l2); split_h(v.w, h3, l3);
    __half* o = out + m * 2 * (size_t)K + k4;
    *(__half2*)(o)         = __halves2half2(h0, h1);
    *(__half2*)(o + 2)     = __halves2half2(h2, h3);
    *(__half2*)(o + K)     = __halves2half2(l0, l1);
    *(__half2*)(o + K + 2) = __halves2half2(l2, l3);
}

struct W4 { const float* w[4]; };

// 4 weights batched: W [in][out] fp32 -> W^T split [out][2*in] fp16
__global__ void wtrans_split(W4 ws, __half* __restrict__ out)
{
    const float* in = ws.w[blockIdx.z];
    __half* o = out + (size_t)blockIdx.z * D_MODEL * 2 * D_MODEL;
    __shared__ float t[32][33];
    int r0 = blockIdx.y * 32, c0 = blockIdx.x * 32;
    t[threadIdx.y][threadIdx.x] = in[(size_t)(r0 + threadIdx.y) * D_MODEL + c0 + threadIdx.x];
    __syncthreads();
    float v = t[threadIdx.x][threadIdx.y];             // in[r0+tx][c0+ty]
    __half h, l;
    split_h(v, h, l);
    size_t oo = (size_t)(c0 + threadIdx.y) * (2 * D_MODEL) + r0 + threadIdx.x;
    o[oo]           = h;
    o[oo + D_MODEL] = l;
}

__global__ __launch_bounds__(256)
void softmax_split_h(const float* __restrict__ S, __half* __restrict__ P)
{
    const float* row = S + (size_t)blockIdx.x * SEQ;
    __half* prow = P + (size_t)blockIdx.x * (2 * SEQ);
    const int tid = threadIdx.x;

    float v[8];
    float m = -3.4e38f;
#pragma unroll
    for (int i = 0; i < 8; i++) { v[i] = row[tid + i * 256]; m = fmaxf(m, v[i]); }

    __shared__ float red[8];
#pragma unroll
    for (int o = 16; o > 0; o >>= 1) m = fmaxf(m, __shfl_xor_sync(0xffffffffu, m, o));
    if ((tid & 31) == 0) red[tid >> 5] = m;
    __syncthreads();
    m = red[0];
#pragma unroll
    for (int w = 1; w < 8; w++) m = fmaxf(m, red[w]);
    __syncthreads();

    float s = 0.f;
#pragma unroll
    for (int i = 0; i < 8; i++) { v[i] = __expf(v[i] - m); s += v[i]; }
#pragma unroll
    for (int o = 16; o > 0; o >>= 1) s += __shfl_xor_sync(0xffffffffu, s, o);
    if ((tid & 31) == 0) red[tid >> 5] = s;
    __syncthreads();
    s = 0.f;
#pragma unroll
    for (int w = 0; w < 8; w++) s += red[w];
    const float inv = 1.f / s;

#pragma unroll
    for (int i = 0; i < 8; i++) {
        float p = v[i] * inv;
        __half h, l;
        split_h(p, h, l);
        prow[tid + i * 256]       = h;
        prow[SEQ + tid + i * 256] = l;
    }
}

// ---------------- host launcher ----------------------------------------------
extern "C" void kernel_launch(void* const* d_in, const int* in_sizes, int n_in,
                              void* d_out, int out_size)
{
    const float* x  = (const float*)d_in[0];
    const float* bq = (const float*)d_in[2];
    const float* bk = (const float*)d_in[4];
    const float* bv = (const float*)d_in[6];
    const float* bo = (const float*)d_in[8];
    float* out = (float*)d_out;

    __half *xs, *wt, *qs, *ks, *vts, *ps, *as;
    float *sc;
    cudaGetSymbolAddress((void**)&xs,  g_xs);
    cudaGetSymbolAddress((void**)&wt,  g_wt);
    cudaGetSymbolAddress((void**)&qs,  g_qs);
    cudaGetSymbolAddress((void**)&ks,  g_ks);
    cudaGetSymbolAddress((void**)&vts, g_vts);
    cudaGetSymbolAddress((void**)&sc,  g_sc);
    cudaGetSymbolAddress((void**)&ps,  g_ps);
    cudaGetSymbolAddress((void**)&as,  g_as);
    const size_t WSTRIDE = (size_t)D_MODEL * 2 * D_MODEL;

    cudaFuncSetAttribute(gemm_mma<OUT_SPLIT, true>,  cudaFuncAttributeMaxDynamicSharedMemorySize, GEMM_SMEM);
    cudaFuncSetAttribute(gemm_mma<OUT_HALF,  true>,  cudaFuncAttributeMaxDynamicSharedMemorySize, GEMM_SMEM);
    cudaFuncSetAttribute(gemm_mma<OUT_VT,    true>,  cudaFuncAttributeMaxDynamicSharedMemorySize, GEMM_SMEM);
    cudaFuncSetAttribute(gemm_mma<OUT_F32,   false>, cudaFuncAttributeMaxDynamicSharedMemorySize, GEMM_SMEM);
    cudaFuncSetAttribute(gemm_mma<OUT_SPLIT, false>, cudaFuncAttributeMaxDynamicSharedMemorySize, GEMM_SMEM);
    cudaFuncSetAttribute(gemm_mma<OUT_F32,   true>,  cudaFuncAttributeMaxDynamicSharedMemorySize, GEMM_SMEM);

    // 1. split x -> xs
    split_rows_h<<<(BS_TOT * (D_MODEL / 4)) / 256, 256>>>(x, xs, D_MODEL);

    // 2. transpose+split all 4 weights in one batched launch
    W4 ws;
    ws.w[0] = (const float*)d_in[1]; ws.w[1] = (const float*)d_in[3];
    ws.w[2] = (const float*)d_in[5]; ws.w[3] = (const float*)d_in[7];
    wtrans_split<<<dim3(32, 32, 4), dim3(32, 32)>>>(ws, wt);

    // 3. q = (x Wq + bq)/32 -> split; M=8192 N=1024 K=1024
    const dim3 gproj(D_MODEL / BN, BS_TOT / BM, 1);
    gemm_mma<OUT_SPLIT, true><<<gproj, 256, GEMM_SMEM>>>(
        xs, wt + 0 * WSTRIDE, bq, qs, D_MODEL, D_MODEL, 2 * D_MODEL, 0.03125f, 0, 0, 0);

    // 4. k = x Wk + bk -> hi-only
    gemm_mma<OUT_HALF, true><<<gproj, 256, GEMM_SMEM>>>(
        xs, wt + 1 * WSTRIDE, bk, ks, D_MODEL, D_MODEL, 2 * D_MODEL, 1.0f, 0, 0, 0);

    // 5. v^T direct: A = Wv^T split (M=1024), B = xs hi (N=8192) -> vts[b][d][t]
    const dim3 gvt(BS_TOT / BN, D_MODEL / BM, 1);
    gemm_mma<OUT_VT, true><<<gvt, 256, GEMM_SMEM>>>(
        wt + 2 * WSTRIDE, xs, bv, vts, BS_TOT, D_MODEL, 2 * D_MODEL, 1.0f, 0, 0, 0);

    // 6. scores = q_scaled @ k^T (batched): M=N=2048, K=1024   <-- profiled launch
    const dim3 gsc(SEQ / BN, SEQ / BM, BATCH);
    gemm_mma<OUT_F32, false><<<gsc, 256, GEMM_SMEM>>>(
        qs, ks, nullptr, sc, SEQ, D_MODEL, D_MODEL, 1.0f,
        (size_t)SEQ * 2 * D_MODEL, (size_t)SEQ * D_MODEL, (size_t)SEQ * SEQ);

    // 7. softmax (+split)
    softmax_split_h<<<BATCH * SEQ, 256>>>(sc, ps);

    // 8. attn = p @ v (batched): M=2048, N=1024, K=2048 (B = vts hi-only)
    const dim3 gpv(D_MODEL / BN, SEQ / BM, BATCH);
    gemm_mma<OUT_SPLIT, false><<<gpv, 256, GEMM_SMEM>>>(
        ps, vts, nullptr, as, D_MODEL, SEQ, SEQ, 1.0f,
        (size_t)SEQ * 2 * SEQ, (size_t)D_MODEL * SEQ, (size_t)SEQ * 2 * D_MODEL);

    // 9. out = attn @ Wo + bo
    gemm_mma<OUT_F32, true><<<gproj, 256, GEMM_SMEM>>>(
        as, wt + 3 * WSTRIDE, bo, out, D_MODEL, D_MODEL, 2 * D_MODEL, 1.0f, 0, 0, 0);
}

// round 5
// speedup vs baseline: 7.0969x; 1.8974x over previous
#include <cuda_runtime.h>
#include <cuda_fp16.h>
#include <cstdint>

#define D_MODEL 1024
#define SEQ     2048
#define BATCH   4
#define BS_TOT  8192

// ---------------- scratch (device globals; no allocations allowed) ----------
__device__ __align__(16) __half g_xs[(size_t)BS_TOT * D_MODEL];            // x fp16
__device__ __align__(16) __half g_wt[4][(size_t)D_MODEL * D_MODEL];        // W^T fp16 x4
__device__ __align__(16) __half g_qs[(size_t)BS_TOT * D_MODEL];            // q fp16 (pre-scaled 1/32)
__device__ __align__(16) __half g_ks[(size_t)BS_TOT * D_MODEL];            // k fp16
__device__ __align__(16) __half g_vts[(size_t)BATCH * D_MODEL * SEQ];      // v^T fp16 [b][1024][2048]
__device__ __align__(16) float  g_sc[(size_t)BATCH * SEQ * SEQ];           // scores fp32
__device__ __align__(16) __half g_ps[(size_t)BATCH * SEQ * SEQ];           // softmax fp16
__device__ __align__(16) __half g_as[(size_t)BS_TOT * D_MODEL];            // attn fp16

// ---------------- helpers ----------------
__device__ __forceinline__ uint32_t s2u(const void* p) {
    uint32_t a;
    asm("{ .reg .u64 t; cvta.to.shared.u64 t, %1; cvt.u32.u64 %0, t; }" : "=r"(a) : "l"(p));
    return a;
}

// smem tile: 128 rows x 64 fp16 (128B rows = 8 x 16B chunks), XOR swizzle.
__device__ __forceinline__ uint32_t swz(int row, int chunk) {
    return (uint32_t)(row * 128 + ((chunk ^ (row & 7)) << 4));
}

__device__ __forceinline__ void ldsm4(uint32_t (&r)[4], uint32_t a) {
    asm volatile("ldmatrix.sync.aligned.m8n8.x4.shared.b16 {%0,%1,%2,%3}, [%4];"
                 : "=r"(r[0]), "=r"(r[1]), "=r"(r[2]), "=r"(r[3]) : "r"(a));
}

__device__ __forceinline__ void mma16816(float (&d)[4], const uint32_t (&a)[4],
                                         uint32_t b0, uint32_t b1) {
    asm volatile(
        "mma.sync.aligned.m16n8k16.row.col.f32.f16.f16.f32 "
        "{%0,%1,%2,%3}, {%4,%5,%6,%7}, {%8,%9}, {%0,%1,%2,%3};"
        : "+f"(d[0]), "+f"(d[1]), "+f"(d[2]), "+f"(d[3])
        : "r"(a[0]), "r"(a[1]), "r"(a[2]), "r"(a[3]), "r"(b0), "r"(b1));
}

// ---------------- plain fp16 GEMM: D = A * B^T -------------------------------
// A: [M][K] fp16 (row stride K). B: [N rows][ldb] fp16, K in cols [0,K).
#define BM 128
#define BN 128
#define BK 64
#define TILE_B  16384                // 128 rows * 128B
#define STAGE_B (2 * TILE_B)         // A + B = 32KB
#define GEMM_SMEM (3 * STAGE_B)      // 3 stages = 96KB

// OUT modes
#define OUT_F32   0
#define OUT_HALF  2   // half [m][N]
#define OUT_VT    3   // half, col n -> (b = n>>11, t = n&2047): C[b][row][t]; bias by row

__device__ __forceinline__ void ld_tile(uint32_t sdst, const __half* src,
                                        size_t ld, int tid) {
#pragma unroll
    for (int j = 0; j < 4; j++) {
        int u = tid + 256 * j;
        int r = u >> 3, c = u & 7;
        uint32_t dst = sdst + swz(r, c);
        const void* s = src + (size_t)r * ld + c * 8;
        asm volatile("cp.async.cg.shared.global [%0], [%1], 16;" :: "r"(dst), "l"(s));
    }
}

template<int MODE, bool HAS_BIAS>
__global__ __launch_bounds__(256, 2)
void gemm_mma(const __half* __restrict__ A,
              const __half* __restrict__ B,
              const float* __restrict__ bias,
              void* __restrict__ Cg,
              int N, int K, int ldb, float alpha,
              size_t sA, size_t sB, size_t sC)
{
    extern __shared__ __align__(128) char smem[];
    const uint32_t sb = s2u(smem);
    const int tid = threadIdx.x, lane = tid & 31, wid = tid >> 5;
    const int wm = wid & 1, wn = wid >> 1;          // 2 x 4 warp grid
    const size_t lda = (size_t)K;

    A += blockIdx.z * sA + (size_t)blockIdx.y * BM * lda;
    B += blockIdx.z * sB + (size_t)blockIdx.x * BN * (size_t)ldb;

    float acc[4][4][4];
#pragma unroll
    for (int i = 0; i < 4; i++)
#pragma unroll
        for (int j = 0; j < 4; j++)
#pragma unroll
            for (int t = 0; t < 4; t++) acc[i][j][t] = 0.f;

    const int NC = K >> 6;     // 64-wide chunks

#pragma unroll
    for (int c = 0; c < 2; c++) {
        uint32_t st = sb + c * STAGE_B;
        ld_tile(st,          A + c * 64, lda, tid);
        ld_tile(st + TILE_B, B + c * 64, ldb, tid);
        asm volatile("cp.async.commit_group;" ::: "memory");
    }

    for (int i = 0; i < NC; i++) {
        asm volatile("cp.async.wait_group 1;" ::: "memory");
        __syncthreads();

        if (i + 2 < NC) {
            int c = i + 2;
            uint32_t st = sb + (c % 3) * STAGE_B;
            ld_tile(st,          A + c * 64, lda, tid);
            ld_tile(st + TILE_B, B + c * 64, ldb, tid);
        }
        asm volatile("cp.async.commit_group;" ::: "memory");

        uint32_t st = sb + (i % 3) * STAGE_B;
        uint32_t sA_ = st, sB_ = st + TILE_B;

#pragma unroll
        for (int ks = 0; ks < 4; ks++) {            // four k16 steps per chunk
            const int arow = lane & 15;
            const int achk = ks * 2 + (lane >> 4);

            uint32_t af[4][4], bf[2][4];
#pragma unroll
            for (int mt = 0; mt < 4; mt++)
                ldsm4(af[mt], sA_ + swz(wm * 64 + mt * 16 + arow, achk));
#pragma unroll
            for (int n2 = 0; n2 < 2; n2++)
                ldsm4(bf[n2], sB_ + swz(wn * 32 + n2 * 16 + arow, achk));

#pragma unroll
            for (int mt = 0; mt < 4; mt++)
#pragma unroll
                for (int nt = 0; nt < 4; nt++) {
                    const int n2 = nt >> 1, sub = nt & 1;
                    mma16816(acc[mt][nt], af[mt], bf[n2][sub], bf[n2][sub + 2]);
                }
        }
    }

    // ---- epilogue ----
    const int gm0 = blockIdx.y * BM + wm * 64;
    const int gn0 = blockIdx.x * BN + wn * 32;
    const int rq = lane >> 2, cq = (lane & 3) * 2;

#pragma unroll
    for (int mt = 0; mt < 4; mt++)
#pragma unroll
        for (int nt = 0; nt < 4; nt++)
#pragma unroll
            for (int h = 0; h < 2; h++) {
                const int row = gm0 + mt * 16 + rq + h * 8;
                const int col = gn0 + nt * 8 + cq;
                float v0 = acc[mt][nt][h * 2 + 0];
                float v1 = acc[mt][nt][h * 2 + 1];
                if (HAS_BIAS) {
                    if (MODE == OUT_VT) { float b = __ldg(&bias[row]); v0 += b; v1 += b; }
                    else { v0 += __ldg(&bias[col]); v1 += __ldg(&bias[col + 1]); }
                }
                v0 *= alpha; v1 *= alpha;
                if (MODE == OUT_HALF) {
                    __half* C = (__half*)Cg + blockIdx.z * sC + (size_t)row * (size_t)N + col;
                    *(__half2*)C = __halves2half2(__float2half_rn(v0), __float2half_rn(v1));
                } else if (MODE == OUT_VT) {
                    const int b = col >> 11, t = col & 2047;
                    __half* C = (__half*)Cg + (size_t)b * D_MODEL * SEQ
                              + (size_t)row * SEQ + t;
                    *(__half2*)C = __halves2half2(__float2half_rn(v0), __float2half_rn(v1));
                } else {
                    float* C = (float*)Cg + blockIdx.z * sC + (size_t)row * (size_t)N + col;
                    float2 v; v.x = v0; v.y = v1;
                    *(float2*)C = v;
                }
            }
}

// ---------------- conversion kernels ----------------------------------------
__global__ __launch_bounds__(256)
void cvt_h(const float* __restrict__ in, __half* __restrict__ out)
{
    size_t i = ((size_t)blockIdx.x * blockDim.x + threadIdx.x) * 4;
    float4 v = *(const float4*)(in + i);
    __half2 a = __halves2half2(__float2half_rn(v.x), __float2half_rn(v.y));
    __half2 b = __halves2half2(__float2half_rn(v.z), __float2half_rn(v.w));
    *(__half2*)(out + i)     = a;
    *(__half2*)(out + i + 2) = b;
}

struct W4 { const float* w[4]; };

// 4 weights batched: W [in][out] fp32 -> W^T [out][in] fp16
__global__ void wtrans_h(W4 ws, __half* __restrict__ out)
{
    const float* in = ws.w[blockIdx.z];
    __half* o = out + (size_t)blockIdx.z * D_MODEL * D_MODEL;
    __shared__ float t[32][33];
    int r0 = blockIdx.y * 32, c0 = blockIdx.x * 32;
    t[threadIdx.y][threadIdx.x] = in[(size_t)(r0 + threadIdx.y) * D_MODEL + c0 + threadIdx.x];
    __syncthreads();
    float v = t[threadIdx.x][threadIdx.y];             // in[r0+tx][c0+ty]
    o[(size_t)(c0 + threadIdx.y) * D_MODEL + r0 + threadIdx.x] = __float2half_rn(v);
}

__global__ __launch_bounds__(256)
void softmax_h(const float* __restrict__ S, __half* __restrict__ P)
{
    const float* row = S + (size_t)blockIdx.x * SEQ;
    __half* prow = P + (size_t)blockIdx.x * SEQ;
    const int tid = threadIdx.x;

    float v[8];
    float m = -3.4e38f;
#pragma unroll
    for (int i = 0; i < 8; i++) { v[i] = row[tid + i * 256]; m = fmaxf(m, v[i]); }

    __shared__ float red[8];
#pragma unroll
    for (int o = 16; o > 0; o >>= 1) m = fmaxf(m, __shfl_xor_sync(0xffffffffu, m, o));
    if ((tid & 31) == 0) red[tid >> 5] = m;
    __syncthreads();
    m = red[0];
#pragma unroll
    for (int w = 1; w < 8; w++) m = fmaxf(m, red[w]);
    __syncthreads();

    float s = 0.f;
#pragma unroll
    for (int i = 0; i < 8; i++) { v[i] = __expf(v[i] - m); s += v[i]; }
#pragma unroll
    for (int o = 16; o > 0; o >>= 1) s += __shfl_xor_sync(0xffffffffu, s, o);
    if ((tid & 31) == 0) red[tid >> 5] = s;
    __syncthreads();
    s = 0.f;
#pragma unroll
    for (int w = 0; w < 8; w++) s += red[w];
    const float inv = 1.f / s;

#pragma unroll
    for (int i = 0; i < 8; i++)
        prow[tid + i * 256] = __float2half_rn(v[i] * inv);
}

// ---------------- host launcher ----------------------------------------------
extern "C" void kernel_launch(void* const* d_in, const int* in_sizes, int n_in,
                              void* d_out, int out_size)
{
    const float* x  = (const float*)d_in[0];
    const float* bq = (const float*)d_in[2];
    const float* bk = (const float*)d_in[4];
    const float* bv = (const float*)d_in[6];
    const float* bo = (const float*)d_in[8];
    float* out = (float*)d_out;

    __half *xs, *wt, *qs, *ks, *vts, *ps, *as;
    float *sc;
    cudaGetSymbolAddress((void**)&xs,  g_xs);
    cudaGetSymbolAddress((void**)&wt,  g_wt);
    cudaGetSymbolAddress((void**)&qs,  g_qs);
    cudaGetSymbolAddress((void**)&ks,  g_ks);
    cudaGetSymbolAddress((void**)&vts, g_vts);
    cudaGetSymbolAddress((void**)&sc,  g_sc);
    cudaGetSymbolAddress((void**)&ps,  g_ps);
    cudaGetSymbolAddress((void**)&as,  g_as);
    const size_t WSTRIDE = (size_t)D_MODEL * D_MODEL;

    cudaFuncSetAttribute(gemm_mma<OUT_HALF, true>,  cudaFuncAttributeMaxDynamicSharedMemorySize, GEMM_SMEM);
    cudaFuncSetAttribute(gemm_mma<OUT_VT,   true>,  cudaFuncAttributeMaxDynamicSharedMemorySize, GEMM_SMEM);
    cudaFuncSetAttribute(gemm_mma<OUT_F32,  false>, cudaFuncAttributeMaxDynamicSharedMemorySize, GEMM_SMEM);
    cudaFuncSetAttribute(gemm_mma<OUT_HALF, false>, cudaFuncAttributeMaxDynamicSharedMemorySize, GEMM_SMEM);
    cudaFuncSetAttribute(gemm_mma<OUT_F32,  true>,  cudaFuncAttributeMaxDynamicSharedMemorySize, GEMM_SMEM);

    // 1. x -> fp16
    cvt_h<<<(BS_TOT * (D_MODEL / 4)) / 256, 256>>>(x, xs);

    // 2. transpose all 4 weights (fp16) in one batched launch
    W4 ws;
    ws.w[0] = (const float*)d_in[1]; ws.w[1] = (const float*)d_in[3];
    ws.w[2] = (const float*)d_in[5]; ws.w[3] = (const float*)d_in[7];
    wtrans_h<<<dim3(32, 32, 4), dim3(32, 32)>>>(ws, wt);

    // 3. q = (x Wq + bq)/32 : M=8192 N=1024 K=1024
    const dim3 gproj(D_MODEL / BN, BS_TOT / BM, 1);
    gemm_mma<OUT_HALF, true><<<gproj, 256, GEMM_SMEM>>>(
        xs, wt + 0 * WSTRIDE, bq, qs, D_MODEL, D_MODEL, D_MODEL, 0.03125f, 0, 0, 0);

    // 4. k = x Wk + bk
    gemm_mma<OUT_HALF, true><<<gproj, 256, GEMM_SMEM>>>(
        xs, wt + 1 * WSTRIDE, bk, ks, D_MODEL, D_MODEL, D_MODEL, 1.0f, 0, 0, 0);

    // 5. v^T direct: A = Wv^T (M=1024), B = xs (N=8192) -> vts[b][d][t]
    const dim3 gvt(BS_TOT / BN, D_MODEL / BM, 1);
    gemm_mma<OUT_VT, true><<<gvt, 256, GEMM_SMEM>>>(
        wt + 2 * WSTRIDE, xs, bv, vts, BS_TOT, D_MODEL, D_MODEL, 1.0f, 0, 0, 0);

    // 6. scores = q_scaled @ k^T (batched): M=N=2048, K=1024
    const dim3 gsc(SEQ / BN, SEQ / BM, BATCH);
    gemm_mma<OUT_F32, false><<<gsc, 256, GEMM_SMEM>>>(
        qs, ks, nullptr, sc, SEQ, D_MODEL, D_MODEL, 1.0f,
        (size_t)SEQ * D_MODEL, (size_t)SEQ * D_MODEL, (size_t)SEQ * SEQ);

    // 7. softmax -> fp16
    softmax_h<<<BATCH * SEQ, 256>>>(sc, ps);

    // 8. attn = p @ v (batched): M=2048, N=1024, K=2048
    const dim3 gpv(D_MODEL / BN, SEQ / BM, BATCH);
    gemm_mma<OUT_HALF, false><<<gpv, 256, GEMM_SMEM>>>(
        ps, vts, nullptr, as, D_MODEL, SEQ, SEQ, 1.0f,
        (size_t)SEQ * SEQ, (size_t)D_MODEL * SEQ, (size_t)SEQ * D_MODEL);

    // 9. out = attn @ Wo + bo
    gemm_mma<OUT_F32, true><<<gproj, 256, GEMM_SMEM>>>(
        as, wt + 3 * WSTRIDE, bo, out, D_MODEL, D_MODEL, D_MODEL, 1.0f, 0, 0, 0);
}